// round 3
// baseline (speedup 1.0000x reference)
#include <cuda_runtime.h>
#include <cstdint>

#define B 64
#define P 8732
#define C 81
#define O 32
#define SLICES 8

#define NEG_INF (__int_as_float(0xff800000))

// ---------------- scratch (device globals; no allocation anywhere) ----------
__device__ unsigned long long g_obj_best[B * O];   // per-object best prior (packed)
__device__ int   g_best_obj[B * P];                // per-prior matched object
__device__ int   g_true_class[B * P];              // per-prior class (0 = bg)
__device__ float g_mined[B * P];                   // bg_loss (neg) / -inf (pos)
__device__ int   g_num_pos[B];
__device__ float g_neg_sum[B];
__device__ float g_pos_ce;
__device__ float g_sl1;

// ---------------- helpers ----------------------------------------------------
__device__ __forceinline__ unsigned okey(float f) {
    unsigned u = __float_as_uint(f);
    return (u & 0x80000000u) ? ~u : (u | 0x80000000u);   // monotone float->uint
}
__device__ __forceinline__ float fromkey(unsigned k) {
    unsigned u = (k & 0x80000000u) ? (k & 0x7FFFFFFFu) : ~k;
    return __uint_as_float(u);
}
__device__ __forceinline__ float smoothl1(float d) {
    float a = fabsf(d);
    return (a < 1.0f) ? 0.5f * a * a : a - 0.5f;
}

// ---------------- K0: init ----------------------------------------------------
__global__ void init_kernel() {
    int t = blockIdx.x * blockDim.x + threadIdx.x;
    if (t < B * O) g_obj_best[t] = 0ULL;
    if (t < B) { g_num_pos[t] = 0; g_neg_sum[t] = 0.0f; }
    if (t == 0) { g_pos_ce = 0.0f; g_sl1 = 0.0f; }
}

// ---------------- K1: matching (IoU, per-prior & per-object argmax) -----------
__global__ void match_kernel(const float* __restrict__ boxes,
                             const int*   __restrict__ labels,
                             const float* __restrict__ priors) {
    int b = blockIdx.x;
    int slice = blockIdx.y;
    __shared__ float4 sbox[O];
    __shared__ float  sarea[O];
    __shared__ int    slab[O];
    __shared__ unsigned long long sbest[O];
    int tid = threadIdx.x;
    if (tid < O) {
        float4 bx = ((const float4*)boxes)[b * O + tid];
        sbox[tid] = bx;
        sarea[tid] = (bx.z - bx.x) * (bx.w - bx.y);
        slab[tid] = labels[b * O + tid];
        sbest[tid] = 0ULL;
    }
    __syncthreads();

    unsigned long long lbest[O];
#pragma unroll
    for (int o = 0; o < O; o++) lbest[o] = 0ULL;

    const int chunk = (P + SLICES - 1) / SLICES;
    int pstart = slice * chunk;
    int pend = min(P, pstart + chunk);

    for (int p = pstart + tid; p < pend; p += blockDim.x) {
        float4 pr = ((const float4*)priors)[p];           // cxcywh
        float px0 = pr.x - 0.5f * pr.z, py0 = pr.y - 0.5f * pr.w;
        float px1 = pr.x + 0.5f * pr.z, py1 = pr.y + 0.5f * pr.w;
        float parea = pr.z * pr.w;
        float best_ov = -1.0f; int best_o = 0;
#pragma unroll
        for (int o = 0; o < O; o++) {
            float4 bx = sbox[o];
            float lx = fmaxf(bx.x, px0), ly = fmaxf(bx.y, py0);
            float hx = fminf(bx.z, px1), hy = fminf(bx.w, py1);
            float w = fmaxf(hx - lx, 0.0f), h = fmaxf(hy - ly, 0.0f);
            float inter = w * h;
            float ov = inter / (sarea[o] + parea - inter);
            if (ov > best_ov) { best_ov = ov; best_o = o; }   // first-max = lowest o
            unsigned long long packed =
                ((unsigned long long)__float_as_uint(ov) << 32) |
                (unsigned)(0xFFFFFFFFu - (unsigned)p);        // lower p wins ties
            if (packed > lbest[o]) lbest[o] = packed;
        }
        int idx = b * P + p;
        g_best_obj[idx] = best_o;
        g_true_class[idx] = (best_ov < 0.5f) ? 0 : slab[best_o];
    }
#pragma unroll
    for (int o = 0; o < O; o++) atomicMax(&sbest[o], lbest[o]);
    __syncthreads();
    if (tid < O) atomicMax(&g_obj_best[b * O + tid], sbest[tid]);
}

// ---------------- K2: scatter (each object owns its best prior, last wins) ----
__global__ void scatter_kernel(const int* __restrict__ labels) {
    int b = blockIdx.x;
    if (threadIdx.x == 0) {
        for (int o = 0; o < O; o++) {                      // serial => last-wins
            unsigned long long pk = g_obj_best[b * O + o];
            int p = (int)(0xFFFFFFFFu - (unsigned)(pk & 0xFFFFFFFFu));
            g_best_obj[b * P + p] = o;
            g_true_class[b * P + p] = labels[b * O + o];
        }
    }
}

// ---------------- K3: log-softmax pass + pos losses + mining scores ----------
__global__ void loss_kernel(const float* __restrict__ locs,
                            const float* __restrict__ scores,
                            const float* __restrict__ boxes,
                            const float* __restrict__ priors) {
    int warp = blockIdx.x * (blockDim.x >> 5) + (threadIdx.x >> 5);
    int lane = threadIdx.x & 31;
    if (warp >= B * P) return;
    int b = warp / P;
    int p = warp - b * P;

    const float* srow = scores + (size_t)warp * C;
    float v0 = srow[lane];
    float v1 = srow[lane + 32];
    float v2 = (lane < C - 64) ? srow[lane + 64] : NEG_INF;

    float m = fmaxf(fmaxf(v0, v1), v2);
#pragma unroll
    for (int off = 16; off; off >>= 1) m = fmaxf(m, __shfl_xor_sync(0xFFFFFFFFu, m, off));
    float s = __expf(v0 - m) + __expf(v1 - m) + ((lane < C - 64) ? __expf(v2 - m) : 0.0f);
#pragma unroll
    for (int off = 16; off; off >>= 1) s += __shfl_xor_sync(0xFFFFFFFFu, s, off);
    float lse = m + __logf(s);

    float s0 = __shfl_sync(0xFFFFFFFFu, v0, 0);
    float bg = lse - s0;

    int tc = g_true_class[warp];                          // uniform across warp
    if (tc > 0) {
        float sv0 = __shfl_sync(0xFFFFFFFFu, v0, tc & 31);
        float sv1 = __shfl_sync(0xFFFFFFFFu, v1, tc & 31);
        float sv2 = __shfl_sync(0xFFFFFFFFu, v2, tc & 31);
        if (lane == 0) {
            float sc = (tc < 32) ? sv0 : ((tc < 64) ? sv1 : sv2);
            atomicAdd(&g_pos_ce, lse - sc);
            atomicAdd(&g_num_pos[b], 1);
            int obj = g_best_obj[warp];
            float4 bx = ((const float4*)boxes)[b * O + obj];
            float4 pr = ((const float4*)priors)[p];
            float cx = 0.5f * (bx.x + bx.z), cy = 0.5f * (bx.y + bx.w);
            float w = bx.z - bx.x, h = bx.w - bx.y;
            float t0 = (cx - pr.x) * 10.0f / pr.z;
            float t1 = (cy - pr.y) * 10.0f / pr.w;
            float t2 = __logf(w / pr.z) * 5.0f;
            float t3 = __logf(h / pr.w) * 5.0f;
            float4 pl = ((const float4*)locs)[warp];
            float sl = smoothl1(pl.x - t0) + smoothl1(pl.y - t1) +
                       smoothl1(pl.z - t2) + smoothl1(pl.w - t3);
            atomicAdd(&g_sl1, sl);
            g_mined[warp] = NEG_INF;
        }
    } else {
        if (lane == 0) g_mined[warp] = bg;
    }
}

// ---------------- K4: per-batch radix-select top-K negatives + sum -----------
__global__ void select_kernel() {
    int b = blockIdx.x;
    const float* mined = g_mined + b * P;
    int np = g_num_pos[b];
    int K = min(3 * np, P - np);

    __shared__ int hist[256];
    __shared__ unsigned sprefix;
    __shared__ int sK;
    __shared__ float swsum[8];
    int tid = threadIdx.x;

    if (tid == 0) { sprefix = 0u; sK = K; }
    __syncthreads();
    if (K <= 0) { if (tid == 0) g_neg_sum[b] = 0.0f; return; }

    for (int shift = 24; shift >= 0; shift -= 8) {
        hist[tid] = 0;
        __syncthreads();
        unsigned prefix = sprefix;
        for (int p = tid; p < P; p += 256) {
            unsigned k = okey(mined[p]);
            if (shift == 24 || (k >> (shift + 8)) == prefix)
                atomicAdd(&hist[(k >> shift) & 255u], 1);
        }
        __syncthreads();
        if (tid == 0) {
            int Kr = sK;
            int bin = 255;
            for (; bin > 0; bin--) {
                if (hist[bin] >= Kr) break;
                Kr -= hist[bin];
            }
            sK = Kr;
            sprefix = (prefix << 8) | (unsigned)bin;
        }
        __syncthreads();
    }
    unsigned T = sprefix;
    int r = sK;
    float Tval = fromkey(T);

    float sum = 0.0f;
    for (int p = tid; p < P; p += 256) {
        float v = mined[p];
        if (okey(v) > T) sum += v;
    }
#pragma unroll
    for (int off = 16; off; off >>= 1) sum += __shfl_xor_sync(0xFFFFFFFFu, sum, off);
    if ((tid & 31) == 0) swsum[tid >> 5] = sum;
    __syncthreads();
    if (tid == 0) {
        float tot = 0.0f;
        for (int i = 0; i < 8; i++) tot += swsum[i];
        g_neg_sum[b] = tot + (float)r * Tval;
    }
}

// ---------------- K5: finalize ------------------------------------------------
__global__ void finalize_kernel(float* __restrict__ out) {
    int t = threadIdx.x;          // 64 threads
    float ns = g_neg_sum[t];
    float np = (float)g_num_pos[t];
#pragma unroll
    for (int off = 16; off; off >>= 1) {
        ns += __shfl_xor_sync(0xFFFFFFFFu, ns, off);
        np += __shfl_xor_sync(0xFFFFFFFFu, np, off);
    }
    __shared__ float a[2], c[2];
    if ((t & 31) == 0) { a[t >> 5] = ns; c[t >> 5] = np; }
    __syncthreads();
    if (t == 0) {
        float totns = a[0] + a[1];
        float n = c[0] + c[1];
        out[0] = (g_pos_ce + totns) / n;
        out[1] = g_sl1 / n;
    }
}

// ---------------- launch ------------------------------------------------------
extern "C" void kernel_launch(void* const* d_in, const int* in_sizes, int n_in,
                              void* d_out, int out_size) {
    const float* locs   = (const float*)d_in[0];   // [B,P,4]
    const float* scores = (const float*)d_in[1];   // [B,P,C]
    const float* boxes  = (const float*)d_in[2];   // [B,O,4] xy
    const int*   labels = (const int*)  d_in[3];   // [B,O]
    const float* priors = (const float*)d_in[4];   // [P,4] cxcywh
    float* out = (float*)d_out;

    init_kernel<<<8, 256>>>();
    match_kernel<<<dim3(B, SLICES), 256>>>(boxes, labels, priors);
    scatter_kernel<<<B, 32>>>(labels);
    {
        int total_warps = B * P;                    // 558848, divisible by 8
        int blocks = total_warps / 8;               // 8 warps / 256-thread block
        loss_kernel<<<blocks, 256>>>(locs, scores, boxes, priors);
    }
    select_kernel<<<B, 256>>>();
    finalize_kernel<<<1, 64>>>(out);
}

// round 4
// speedup vs baseline: 1.4261x; 1.4261x over previous
#include <cuda_runtime.h>
#include <cstdint>

#define B 64
#define P 8732
#define C 81
#define O 32
#define RPB 128          // rows per block in loss kernel (B*P = 558848 = 128*4366)

#define NEG_INF (__int_as_float(0xff800000))

// ---------------- scratch (device globals; no allocation anywhere) ----------
__device__ unsigned long long g_obj_best[B * O];   // per-object best prior (packed iou|~p)
__device__ int   g_best_obj[B * P];                // per-prior matched object
__device__ int   g_true_class[B * P];              // per-prior class (0 = bg)
__device__ float g_mined[B * P];                   // bg_loss (neg) / -inf (pos)
__device__ int   g_num_pos[B];
__device__ float g_neg_sum[B];
__device__ float g_pos_ce;
__device__ float g_sl1;

// ---------------- helpers ----------------------------------------------------
__device__ __forceinline__ unsigned okey(float f) {
    unsigned u = __float_as_uint(f);
    return (u & 0x80000000u) ? ~u : (u | 0x80000000u);   // monotone float->uint
}
__device__ __forceinline__ float fromkey(unsigned k) {
    unsigned u = (k & 0x80000000u) ? (k & 0x7FFFFFFFu) : ~k;
    return __uint_as_float(u);
}
__device__ __forceinline__ float smoothl1(float d) {
    float a = fabsf(d);
    return (a < 1.0f) ? 0.5f * a * a : a - 0.5f;
}
__device__ __forceinline__ float iou(float4 bx, float barea,
                                     float px0, float py0, float px1, float py1,
                                     float parea) {
    float lx = fmaxf(bx.x, px0), ly = fmaxf(bx.y, py0);
    float hx = fminf(bx.z, px1), hy = fminf(bx.w, py1);
    float w = fmaxf(hx - lx, 0.0f), h = fmaxf(hy - ly, 0.0f);
    float inter = w * h;
    return inter / (barea + parea - inter);
}

// ---------------- K0: init ----------------------------------------------------
__global__ void init_kernel() {
    int t = threadIdx.x;   // 64 threads
    g_num_pos[t] = 0;
    g_neg_sum[t] = 0.0f;
    if (t == 0) { g_pos_ce = 0.0f; g_sl1 = 0.0f; }
}

// ---------------- K1a: per-prior argmax over objects (thread per prior) ------
__global__ void prior_match_kernel(const float* __restrict__ boxes,
                                   const int*   __restrict__ labels,
                                   const float* __restrict__ priors) {
    int b = blockIdx.y;
    int p = blockIdx.x * 256 + threadIdx.x;
    __shared__ float4 sbox[O];
    __shared__ float  sarea[O];
    __shared__ int    slab[O];
    if (threadIdx.x < O) {
        float4 bx = ((const float4*)boxes)[b * O + threadIdx.x];
        sbox[threadIdx.x] = bx;
        sarea[threadIdx.x] = (bx.z - bx.x) * (bx.w - bx.y);
        slab[threadIdx.x] = labels[b * O + threadIdx.x];
    }
    __syncthreads();
    if (p >= P) return;

    float4 pr = ((const float4*)priors)[p];       // cxcywh
    float px0 = pr.x - 0.5f * pr.z, py0 = pr.y - 0.5f * pr.w;
    float px1 = pr.x + 0.5f * pr.z, py1 = pr.y + 0.5f * pr.w;
    float parea = pr.z * pr.w;

    float best_ov = -1.0f; int best_o = 0;
#pragma unroll
    for (int o = 0; o < O; o++) {
        float ov = iou(sbox[o], sarea[o], px0, py0, px1, py1, parea);
        if (ov > best_ov) { best_ov = ov; best_o = o; }    // first max = lowest o
    }
    int idx = b * P + p;
    g_best_obj[idx] = best_o;
    g_true_class[idx] = (best_ov < 0.5f) ? 0 : slab[best_o];
}

// ---------------- K1b: per-object best prior (block per (o,b)) ---------------
__global__ void object_match_kernel(const float* __restrict__ boxes,
                                    const float* __restrict__ priors) {
    int o = blockIdx.x;
    int b = blockIdx.y;
    int tid = threadIdx.x;                         // 256 threads
    float4 bx = ((const float4*)boxes)[b * O + o];
    float barea = (bx.z - bx.x) * (bx.w - bx.y);

    unsigned long long best = 0ULL;
    for (int p = tid; p < P; p += 256) {
        float4 pr = ((const float4*)priors)[p];
        float px0 = pr.x - 0.5f * pr.z, py0 = pr.y - 0.5f * pr.w;
        float px1 = pr.x + 0.5f * pr.z, py1 = pr.y + 0.5f * pr.w;
        float parea = pr.z * pr.w;
        float ov = iou(bx, barea, px0, py0, px1, py1, parea);   // ov >= 0
        unsigned long long packed =
            ((unsigned long long)__float_as_uint(ov) << 32) |
            (unsigned)(0xFFFFFFFFu - (unsigned)p);              // lower p wins ties
        if (packed > best) best = packed;
    }
    __shared__ unsigned long long red[256];
    red[tid] = best;
    __syncthreads();
#pragma unroll
    for (int s = 128; s > 0; s >>= 1) {
        if (tid < s) red[tid] = max(red[tid], red[tid + s]);
        __syncthreads();
    }
    if (tid == 0) g_obj_best[b * O + o] = red[0];
}

// ---------------- K2: scatter (each object owns its best prior, last wins) ----
__global__ void scatter_kernel(const int* __restrict__ labels) {
    int b = blockIdx.x;
    if (threadIdx.x == 0) {
        for (int o = 0; o < O; o++) {                      // serial => last-wins
            unsigned long long pk = g_obj_best[b * O + o];
            int p = (int)(0xFFFFFFFFu - (unsigned)(pk & 0xFFFFFFFFu));
            g_best_obj[b * P + p] = o;
            g_true_class[b * P + p] = labels[b * O + o];
        }
    }
}

// ---------------- K3: smem-tiled log-softmax + losses + mining scores --------
__global__ void __launch_bounds__(RPB) loss_kernel(const float* __restrict__ locs,
                            const float* __restrict__ scores,
                            const float* __restrict__ boxes,
                            const float* __restrict__ priors) {
    __shared__ float sm[RPB * C];                  // 41472 bytes
    size_t row0 = (size_t)blockIdx.x * RPB;

    // stage 128 rows flat (16B-aligned: 128*81*4 = 41472 ≡ 0 mod 16)
    const float4* src = (const float4*)(scores + row0 * C);
    float4* dst = (float4*)sm;
    const int N4 = RPB * C / 4;                    // 2592
#pragma unroll 4
    for (int i = threadIdx.x; i < N4; i += RPB) dst[i] = src[i];
    __syncthreads();

    int r = (int)row0 + threadIdx.x;
    int b = r / P;
    int p = r - b * P;
    const float* my = sm + threadIdx.x * C;        // stride 81 words: conflict-free

    float s0 = 0.f, s1 = 0.f, s2 = 0.f, s3 = 0.f;
#pragma unroll
    for (int j = 0; j < 80; j += 4) {
        s0 += __expf(my[j]);
        s1 += __expf(my[j + 1]);
        s2 += __expf(my[j + 2]);
        s3 += __expf(my[j + 3]);
    }
    float sum = ((s0 + s1) + (s2 + s3)) + __expf(my[80]);
    float lse = __logf(sum);

    int tc = g_true_class[r];
    float mined;
    if (tc > 0) {
        atomicAdd(&g_pos_ce, lse - my[tc]);
        atomicAdd(&g_num_pos[b], 1);
        int obj = g_best_obj[r];
        float4 bx = ((const float4*)boxes)[b * O + obj];
        float4 pr = ((const float4*)priors)[p];
        float cx = 0.5f * (bx.x + bx.z), cy = 0.5f * (bx.y + bx.w);
        float w = bx.z - bx.x, h = bx.w - bx.y;
        float t0 = (cx - pr.x) * 10.0f / pr.z;
        float t1 = (cy - pr.y) * 10.0f / pr.w;
        float t2 = __logf(w / pr.z) * 5.0f;
        float t3 = __logf(h / pr.w) * 5.0f;
        float4 pl = ((const float4*)locs)[r];
        float sl = smoothl1(pl.x - t0) + smoothl1(pl.y - t1) +
                   smoothl1(pl.z - t2) + smoothl1(pl.w - t3);
        atomicAdd(&g_sl1, sl);
        mined = NEG_INF;
    } else {
        mined = lse - my[0];
    }
    g_mined[r] = mined;
}

// ---------------- K4: per-batch radix-select top-K negatives + sum -----------
__global__ void select_kernel() {
    int b = blockIdx.x;
    const float* mined = g_mined + b * P;
    int np = g_num_pos[b];
    int K = min(3 * np, P - np);

    __shared__ int hist[256];
    __shared__ unsigned sprefix;
    __shared__ int sK;
    __shared__ float swsum[8];
    int tid = threadIdx.x;

    if (tid == 0) { sprefix = 0u; sK = K; }
    __syncthreads();
    if (K <= 0) { if (tid == 0) g_neg_sum[b] = 0.0f; return; }

    for (int shift = 24; shift >= 0; shift -= 8) {
        hist[tid] = 0;
        __syncthreads();
        unsigned prefix = sprefix;
        for (int p = tid; p < P; p += 256) {
            unsigned k = okey(mined[p]);
            if (shift == 24 || (k >> (shift + 8)) == prefix)
                atomicAdd(&hist[(k >> shift) & 255u], 1);
        }
        __syncthreads();
        if (tid == 0) {
            int Kr = sK;
            int bin = 255;
            for (; bin > 0; bin--) {
                if (hist[bin] >= Kr) break;
                Kr -= hist[bin];
            }
            sK = Kr;
            sprefix = (sprefix << 8) | (unsigned)bin;
        }
        __syncthreads();
    }
    unsigned T = sprefix;
    int r = sK;
    float Tval = fromkey(T);

    float sum = 0.0f;
    for (int p = tid; p < P; p += 256) {
        float v = mined[p];
        if (okey(v) > T) sum += v;
    }
#pragma unroll
    for (int off = 16; off; off >>= 1) sum += __shfl_xor_sync(0xFFFFFFFFu, sum, off);
    if ((tid & 31) == 0) swsum[tid >> 5] = sum;
    __syncthreads();
    if (tid == 0) {
        float tot = 0.0f;
        for (int i = 0; i < 8; i++) tot += swsum[i];
        g_neg_sum[b] = tot + (float)r * Tval;
    }
}

// ---------------- K5: finalize ------------------------------------------------
__global__ void finalize_kernel(float* __restrict__ out) {
    int t = threadIdx.x;          // 64 threads
    float ns = g_neg_sum[t];
    float np = (float)g_num_pos[t];
#pragma unroll
    for (int off = 16; off; off >>= 1) {
        ns += __shfl_xor_sync(0xFFFFFFFFu, ns, off);
        np += __shfl_xor_sync(0xFFFFFFFFu, np, off);
    }
    __shared__ float a[2], c[2];
    if ((t & 31) == 0) { a[t >> 5] = ns; c[t >> 5] = np; }
    __syncthreads();
    if (t == 0) {
        float totns = a[0] + a[1];
        float n = c[0] + c[1];
        out[0] = (g_pos_ce + totns) / n;
        out[1] = g_sl1 / n;
    }
}

// ---------------- launch ------------------------------------------------------
extern "C" void kernel_launch(void* const* d_in, const int* in_sizes, int n_in,
                              void* d_out, int out_size) {
    const float* locs   = (const float*)d_in[0];   // [B,P,4]
    const float* scores = (const float*)d_in[1];   // [B,P,C]
    const float* boxes  = (const float*)d_in[2];   // [B,O,4] xy
    const int*   labels = (const int*)  d_in[3];   // [B,O]
    const float* priors = (const float*)d_in[4];   // [P,4] cxcywh
    float* out = (float*)d_out;

    init_kernel<<<1, 64>>>();
    prior_match_kernel<<<dim3((P + 255) / 256, B), 256>>>(boxes, labels, priors);
    object_match_kernel<<<dim3(O, B), 256>>>(boxes, priors);
    scatter_kernel<<<B, 32>>>(labels);
    loss_kernel<<<(B * P) / RPB, RPB>>>(locs, scores, boxes, priors);
    select_kernel<<<B, 256>>>();
    finalize_kernel<<<1, 64>>>(out);
}